// round 10
// baseline (speedup 1.0000x reference)
#include <cuda_runtime.h>

// Problem constants
#define NB 16
#define NT 256
#define NK 128
#define ND 256   // D_E == D_K == 256
#define NU 128

// Scratch (allocation-free rule: __device__ globals)
// Et duplicated (v,v) so score-phase FFMA2 needs no packing movs.
__device__ float2 g_Et2[NB * NT * NU];   // [b*NT+t][u] : (exp(2e), exp(2e))
__device__ float  g_EkT[NB * NU * NK];   // [b][u][k]   : exp(2kp), transposed

// exp(clamp(2x)) — tanh(a+b) factorization: tanh = 1 - 2/(1 + e^{2a}e^{2b})
__device__ __forceinline__ float eclamp(float x) {
    return __expf(fminf(fmaxf(2.0f * x, -16.0f), 16.0f));
}

// Packed f32x2 ops (sm_100+)
__device__ __forceinline__ unsigned long long fma2(unsigned long long a,
                                                   unsigned long long b,
                                                   unsigned long long c) {
    unsigned long long d;
    asm("fma.rn.f32x2 %0, %1, %2, %3;" : "=l"(d) : "l"(a), "l"(b), "l"(c));
    return d;
}
__device__ __forceinline__ unsigned long long mul2(unsigned long long a,
                                                   unsigned long long b) {
    unsigned long long d;
    asm("mul.rn.f32x2 %0, %1, %2;" : "=l"(d) : "l"(a), "l"(b));
    return d;
}
// packed reciprocal: 2x rcp.approx
__device__ __forceinline__ unsigned long long rcp2(unsigned long long v) {
    unsigned long long r;
    asm("{\n\t"
        ".reg .f32 lo, hi, rl, rh;\n\t"
        "mov.b64 {lo, hi}, %1;\n\t"
        "rcp.approx.f32 rl, lo;\n\t"
        "rcp.approx.f32 rh, hi;\n\t"
        "mov.b64 %0, {rl, rh};\n\t"
        "}" : "=l"(r) : "l"(v));
    return r;
}
__device__ __forceinline__ float2 u2f(unsigned long long v) {
    float2 r;
    asm("mov.b64 {%0, %1}, %2;" : "=f"(r.x), "=f"(r.y) : "l"(v));
    return r;
}

#define ONE2 0x3F8000003F800000ull   // packed (1.0f, 1.0f)

// ---------------------------------------------------------------------------
// Projection kernel (R5-proven scalar tiling + exp epilogue):
//   blocks [0,256):   Et = exp(2*(enc@W1+b1))  -> g_Et2 duplicated
//   blocks [256,384): Ek = exp(2*(knw@W2+b2))  -> g_EkT transposed
// ---------------------------------------------------------------------------
__global__ __launch_bounds__(256) void proj_kernel(
    const float* __restrict__ enc, const float* __restrict__ knw,
    const float* __restrict__ W1, const float* __restrict__ b1,
    const float* __restrict__ W2, const float* __restrict__ b2)
{
    const int blk = blockIdx.x;
    const bool isE = (blk < 256);
    const float* __restrict__ A    = isE ? enc : knw;
    const float* __restrict__ W    = isE ? W1  : W2;
    const float* __restrict__ bias = isE ? b1  : b2;
    const int row0 = (isE ? blk : (blk - 256)) * 16;

    __shared__ float As[16][32];
    __shared__ float Bs[32][128];

    const int tid = threadIdx.x;
    const int tx  = tid & 31;
    const int ty  = tid >> 5;

    float4 acc0 = make_float4(0.f, 0.f, 0.f, 0.f);
    float4 acc1 = make_float4(0.f, 0.f, 0.f, 0.f);

    for (int kc = 0; kc < ND; kc += 32) {
        if (tid < 128) {
            int r  = tid >> 3;
            int c4 = tid & 7;
            float4 a = *(const float4*)&A[(row0 + r) * ND + kc + c4 * 4];
            *(float4*)&As[r][c4 * 4] = a;
        }
        #pragma unroll
        for (int i = 0; i < 4; i++) {
            int lin = tid + i * 256;
            int r   = lin >> 5;
            int c4  = lin & 31;
            *(float4*)&Bs[r][c4 * 4] = *(const float4*)&W[(kc + r) * NU + c4 * 4];
        }
        __syncthreads();

        #pragma unroll
        for (int kk = 0; kk < 32; kk++) {
            float4 bv = *(float4*)&Bs[kk][tx * 4];
            float a0 = As[ty * 2 + 0][kk];
            float a1 = As[ty * 2 + 1][kk];
            acc0.x += a0 * bv.x; acc0.y += a0 * bv.y;
            acc0.z += a0 * bv.z; acc0.w += a0 * bv.w;
            acc1.x += a1 * bv.x; acc1.y += a1 * bv.y;
            acc1.z += a1 * bv.z; acc1.w += a1 * bv.w;
        }
        __syncthreads();
    }

    float4 bb = *(const float4*)&bias[tx * 4];
    // exp(clamp(2*(acc+bias)))
    float e00 = eclamp(acc0.x + bb.x), e01 = eclamp(acc0.y + bb.y);
    float e02 = eclamp(acc0.z + bb.z), e03 = eclamp(acc0.w + bb.w);
    float e10 = eclamp(acc1.x + bb.x), e11 = eclamp(acc1.y + bb.y);
    float e12 = eclamp(acc1.z + bb.z), e13 = eclamp(acc1.w + bb.w);

    const int r0 = row0 + ty * 2;
    if (isE) {
        float4* d0 = (float4*)(g_Et2 + (size_t)(r0 + 0) * NU + 4 * tx);
        d0[0] = make_float4(e00, e00, e01, e01);
        d0[1] = make_float4(e02, e02, e03, e03);
        float4* d1 = (float4*)(g_Et2 + (size_t)(r0 + 1) * NU + 4 * tx);
        d1[0] = make_float4(e10, e10, e11, e11);
        d1[1] = make_float4(e12, e12, e13, e13);
    } else {
        int b0 = r0 >> 7;
        int k0 = r0 & 127;
        float* dst = &g_EkT[b0 * NU * NK];
        dst[(4 * tx + 0) * NK + k0] = e00;
        dst[(4 * tx + 1) * NK + k0] = e01;
        dst[(4 * tx + 2) * NK + k0] = e02;
        dst[(4 * tx + 3) * NK + k0] = e03;
        dst[(4 * tx + 0) * NK + k0 + 1] = e10;
        dst[(4 * tx + 1) * NK + k0 + 1] = e11;
        dst[(4 * tx + 2) * NK + k0 + 1] = e12;
        dst[(4 * tx + 3) * NK + k0 + 1] = e13;
    }
}

// ---------------------------------------------------------------------------
// Fused score + softmax + context (R5-proven structure).
// Grid (NT/32, NB) = 128 blocks, 256 threads (8 warps); warp owns 4 t's,
// lane owns k = 4*lane..+3.
// score[t,k] (up to softmax-invariant const) = sum_u -2*V_u / (1 + Et*Ek),
// two u-terms share one rcp:  V0/q0 + V1/q1 = (V0*q1 + V1*q0) / (q0*q1).
// smem: know[128][256] 128KB | EkT[128][128] 64KB |
//       Et2[32][128] float2 32KB (reused as duplicated attn) | v2 1KB
//       = 230400 B (1 CTA/SM)
// ---------------------------------------------------------------------------
__global__ __launch_bounds__(256) void fused_kernel(
    const float* __restrict__ knw, const float* __restrict__ V,
    float* __restrict__ out)
{
    extern __shared__ float smem[];
    float*  know_s = smem;                          // 32768 floats
    float*  EkT_s  = smem + NK * ND;                // 16384 floats
    float2* Et2_s  = (float2*)(EkT_s + NU * NK);    // 4096 float2
    float2* v2_s   = Et2_s + 32 * NU;               // 128 float2

    const int b    = blockIdx.y;
    const int t0   = blockIdx.x * 32;
    const int tid  = threadIdx.x;
    const int lane = tid & 31;
    const int w    = tid >> 5;

    // ---- stage (float4, coalesced) ----
    {
        const float4* s = (const float4*)(knw + b * NK * ND);
        float4* d = (float4*)know_s;
        #pragma unroll
        for (int i = 0; i < 32; i++) d[tid + i * 256] = s[tid + i * 256];
    }
    {
        const float4* s = (const float4*)(g_EkT + b * NU * NK);
        float4* d = (float4*)EkT_s;
        #pragma unroll
        for (int i = 0; i < 16; i++) d[tid + i * 256] = s[tid + i * 256];
    }
    {
        const float4* s = (const float4*)(g_Et2 + (size_t)(b * NT + t0) * NU);
        float4* d = (float4*)Et2_s;
        #pragma unroll
        for (int i = 0; i < 8; i++) d[tid + i * 256] = s[tid + i * 256];
    }
    if (tid < NU) {
        float vv = -2.0f * V[tid];
        v2_s[tid] = make_float2(vv, vv);
    }
    __syncthreads();

    const int tl = 4 * w;   // first local t this warp owns

    // ---- score: acc[tt][0]=(k0,k1) packed, acc[tt][1]=(k2,k3) packed ----
    unsigned long long acc[4][2];
    #pragma unroll
    for (int tt = 0; tt < 4; tt++) { acc[tt][0] = 0ull; acc[tt][1] = 0ull; }

    #pragma unroll 2
    for (int u = 0; u < NU; u += 2) {
        ulonglong2 ek0 = ((const ulonglong2*)&EkT_s[(u + 0) * NK])[lane];
        ulonglong2 ek1 = ((const ulonglong2*)&EkT_s[(u + 1) * NK])[lane];
        unsigned long long v0 = *(const unsigned long long*)&v2_s[u + 0];
        unsigned long long v1 = *(const unsigned long long*)&v2_s[u + 1];
        #pragma unroll
        for (int tt = 0; tt < 4; tt++) {
            unsigned long long et0 =
                *(const unsigned long long*)&Et2_s[(tl + tt) * NU + u + 0];
            unsigned long long et1 =
                *(const unsigned long long*)&Et2_s[(tl + tt) * NU + u + 1];
            // k-slots (0,1)
            unsigned long long q0 = fma2(et0, ek0.x, ONE2);
            unsigned long long q1 = fma2(et1, ek1.x, ONE2);
            unsigned long long num = fma2(v0, q1, mul2(v1, q0));
            acc[tt][0] = fma2(num, rcp2(mul2(q0, q1)), acc[tt][0]);
            // k-slots (2,3)
            q0 = fma2(et0, ek0.y, ONE2);
            q1 = fma2(et1, ek1.y, ONE2);
            num = fma2(v0, q1, mul2(v1, q0));
            acc[tt][1] = fma2(num, rcp2(mul2(q0, q1)), acc[tt][1]);
        }
    }

    // ---- softmax over K (in-warp); constants cancel ----
    #pragma unroll
    for (int tt = 0; tt < 4; tt++) {
        float2 axy = u2f(acc[tt][0]);
        float2 azw = u2f(acc[tt][1]);
        float4 sv = make_float4(axy.x, axy.y, azw.x, azw.y);
        float m = fmaxf(fmaxf(sv.x, sv.y), fmaxf(sv.z, sv.w));
        #pragma unroll
        for (int o = 16; o > 0; o >>= 1)
            m = fmaxf(m, __shfl_xor_sync(0xffffffffu, m, o));
        float4 p;
        p.x = __expf(sv.x - m);
        p.y = __expf(sv.y - m);
        p.z = __expf(sv.z - m);
        p.w = __expf(sv.w - m);
        float sum = (p.x + p.y) + (p.z + p.w);
        #pragma unroll
        for (int o = 16; o > 0; o >>= 1)
            sum += __shfl_xor_sync(0xffffffffu, sum, o);
        float inv = __fdividef(1.0f, sum);
        p.x *= inv; p.y *= inv; p.z *= inv; p.w *= inv;
        // overwrite OWN Et2 row with duplicated attn (p,p); row = 128 float2
        float2* arow = Et2_s + (tl + tt) * NU;
        arow[4 * lane + 0] = make_float2(p.x, p.x);
        arow[4 * lane + 1] = make_float2(p.y, p.y);
        arow[4 * lane + 2] = make_float2(p.z, p.z);
        arow[4 * lane + 3] = make_float2(p.w, p.w);
    }
    __syncwarp();

    // ---- context (FFMA2): out[t][d] = sum_k attn[t][k] * know[k][d] ----
    unsigned long long c[4][4];
    #pragma unroll
    for (int i = 0; i < 4; i++)
        #pragma unroll
        for (int j = 0; j < 4; j++) c[i][j] = 0ull;

    #pragma unroll 4
    for (int k = 0; k < NK; k++) {
        const float* row = &know_s[k * ND];
        ulonglong2 lo = ((const ulonglong2*)row)[lane];        // d=4*lane..+3
        ulonglong2 hi = ((const ulonglong2*)row)[lane + 32];   // d=128+4*lane..+3
        #pragma unroll
        for (int tt = 0; tt < 4; tt++) {
            unsigned long long a =
                *(const unsigned long long*)&Et2_s[(tl + tt) * NU + k];
            c[tt][0] = fma2(a, lo.x, c[tt][0]);
            c[tt][1] = fma2(a, lo.y, c[tt][1]);
            c[tt][2] = fma2(a, hi.x, c[tt][2]);
            c[tt][3] = fma2(a, hi.y, c[tt][3]);
        }
    }

    #pragma unroll
    for (int tt = 0; tt < 4; tt++) {
        float* o = out + (size_t)(b * NT + t0 + tl + tt) * ND;
        ((ulonglong2*)o)[lane]      = make_ulonglong2(c[tt][0], c[tt][1]);
        ((ulonglong2*)o)[lane + 32] = make_ulonglong2(c[tt][2], c[tt][3]);
    }
}

// ---------------------------------------------------------------------------
// Launch
// ---------------------------------------------------------------------------
extern "C" void kernel_launch(void* const* d_in, const int* in_sizes, int n_in,
                              void* d_out, int out_size)
{
    const float* knw = (const float*)d_in[0];   // knowledge_onehot [16,128,256]
    const float* enc = (const float*)d_in[1];   // encoder_outputs  [16,256,256]
    const float* W1  = (const float*)d_in[2];
    const float* b1  = (const float*)d_in[3];
    const float* W2  = (const float*)d_in[4];
    const float* b2  = (const float*)d_in[5];
    const float* V   = (const float*)d_in[6];
    // d_in[7] = bV: cancels in softmax. Unused.

    if (n_in >= 2 && in_sizes[0] == NB * NT * ND && in_sizes[1] == NB * NK * ND) {
        const float* tmp = knw; knw = enc; enc = tmp;
    }

    // 32768 + 16384 + 8192 + 256 floats = 230400 bytes
    const int smem_bytes = (NK * ND + NU * NK + 32 * NU * 2 + NU * 2) * (int)sizeof(float);
    cudaFuncSetAttribute(fused_kernel, cudaFuncAttributeMaxDynamicSharedMemorySize,
                         smem_bytes);

    proj_kernel<<<384, 256>>>(enc, knw, W1, b1, W2, b2);

    dim3 grid(NT / 32, NB);
    fused_kernel<<<grid, 256, smem_bytes>>>(knw, V, (float*)d_out);

    (void)n_in; (void)out_size;
}

// round 11
// speedup vs baseline: 1.0040x; 1.0040x over previous
#include <cuda_runtime.h>

// Problem constants
#define NB 16
#define NT 256
#define NK 128
#define ND 256   // D_E == D_K == 256
#define NU 128

// Scratch (allocation-free rule: __device__ globals)
// Et duplicated (v,v) so score-phase FFMA2 needs no packing movs.
__device__ float2 g_Et2[NB * NT * NU];   // [b*NT+t][u] : (exp(2e), exp(2e))
__device__ float  g_EkT[NB * NU * NK];   // [b][u][k]   : exp(2kp), transposed

// exp(clamp(2x)) — tanh(a+b) factorization: tanh = 1 - 2/(1 + e^{2a}e^{2b})
__device__ __forceinline__ float eclamp(float x) {
    return __expf(fminf(fmaxf(2.0f * x, -16.0f), 16.0f));
}

// Packed f32x2 ops (sm_100+)
__device__ __forceinline__ unsigned long long fma2(unsigned long long a,
                                                   unsigned long long b,
                                                   unsigned long long c) {
    unsigned long long d;
    asm("fma.rn.f32x2 %0, %1, %2, %3;" : "=l"(d) : "l"(a), "l"(b), "l"(c));
    return d;
}
__device__ __forceinline__ unsigned long long mul2(unsigned long long a,
                                                   unsigned long long b) {
    unsigned long long d;
    asm("mul.rn.f32x2 %0, %1, %2;" : "=l"(d) : "l"(a), "l"(b));
    return d;
}
// packed reciprocal: 2x rcp.approx
__device__ __forceinline__ unsigned long long rcp2(unsigned long long v) {
    unsigned long long r;
    asm("{\n\t"
        ".reg .f32 lo, hi, rl, rh;\n\t"
        "mov.b64 {lo, hi}, %1;\n\t"
        "rcp.approx.f32 rl, lo;\n\t"
        "rcp.approx.f32 rh, hi;\n\t"
        "mov.b64 %0, {rl, rh};\n\t"
        "}" : "=l"(r) : "l"(v));
    return r;
}
__device__ __forceinline__ float2 u2f(unsigned long long v) {
    float2 r;
    asm("mov.b64 {%0, %1}, %2;" : "=f"(r.x), "=f"(r.y) : "l"(v));
    return r;
}

#define ONE2 0x3F8000003F800000ull   // packed (1.0f, 1.0f)

// ---------------------------------------------------------------------------
// Projection kernel (R5-proven scalar tiling + exp epilogue):
//   blocks [0,256):   Et = exp(2*(enc@W1+b1))  -> g_Et2 duplicated
//   blocks [256,384): Ek = exp(2*(knw@W2+b2))  -> g_EkT transposed
// ---------------------------------------------------------------------------
__global__ __launch_bounds__(256) void proj_kernel(
    const float* __restrict__ enc, const float* __restrict__ knw,
    const float* __restrict__ W1, const float* __restrict__ b1,
    const float* __restrict__ W2, const float* __restrict__ b2)
{
    const int blk = blockIdx.x;
    const bool isE = (blk < 256);
    const float* __restrict__ A    = isE ? enc : knw;
    const float* __restrict__ W    = isE ? W1  : W2;
    const float* __restrict__ bias = isE ? b1  : b2;
    const int row0 = (isE ? blk : (blk - 256)) * 16;

    __shared__ float As[16][32];
    __shared__ float Bs[32][128];

    const int tid = threadIdx.x;
    const int tx  = tid & 31;
    const int ty  = tid >> 5;

    float4 acc0 = make_float4(0.f, 0.f, 0.f, 0.f);
    float4 acc1 = make_float4(0.f, 0.f, 0.f, 0.f);

    for (int kc = 0; kc < ND; kc += 32) {
        if (tid < 128) {
            int r  = tid >> 3;
            int c4 = tid & 7;
            float4 a = *(const float4*)&A[(row0 + r) * ND + kc + c4 * 4];
            *(float4*)&As[r][c4 * 4] = a;
        }
        #pragma unroll
        for (int i = 0; i < 4; i++) {
            int lin = tid + i * 256;
            int r   = lin >> 5;
            int c4  = lin & 31;
            *(float4*)&Bs[r][c4 * 4] = *(const float4*)&W[(kc + r) * NU + c4 * 4];
        }
        __syncthreads();

        #pragma unroll
        for (int kk = 0; kk < 32; kk++) {
            float4 bv = *(float4*)&Bs[kk][tx * 4];
            float a0 = As[ty * 2 + 0][kk];
            float a1 = As[ty * 2 + 1][kk];
            acc0.x += a0 * bv.x; acc0.y += a0 * bv.y;
            acc0.z += a0 * bv.z; acc0.w += a0 * bv.w;
            acc1.x += a1 * bv.x; acc1.y += a1 * bv.y;
            acc1.z += a1 * bv.z; acc1.w += a1 * bv.w;
        }
        __syncthreads();
    }

    float4 bb = *(const float4*)&bias[tx * 4];
    // exp(clamp(2*(acc+bias)))
    float e00 = eclamp(acc0.x + bb.x), e01 = eclamp(acc0.y + bb.y);
    float e02 = eclamp(acc0.z + bb.z), e03 = eclamp(acc0.w + bb.w);
    float e10 = eclamp(acc1.x + bb.x), e11 = eclamp(acc1.y + bb.y);
    float e12 = eclamp(acc1.z + bb.z), e13 = eclamp(acc1.w + bb.w);

    const int r0 = row0 + ty * 2;
    if (isE) {
        float4* d0 = (float4*)(g_Et2 + (size_t)(r0 + 0) * NU + 4 * tx);
        d0[0] = make_float4(e00, e00, e01, e01);
        d0[1] = make_float4(e02, e02, e03, e03);
        float4* d1 = (float4*)(g_Et2 + (size_t)(r0 + 1) * NU + 4 * tx);
        d1[0] = make_float4(e10, e10, e11, e11);
        d1[1] = make_float4(e12, e12, e13, e13);
    } else {
        int b0 = r0 >> 7;
        int k0 = r0 & 127;
        float* dst = &g_EkT[b0 * NU * NK];
        dst[(4 * tx + 0) * NK + k0] = e00;
        dst[(4 * tx + 1) * NK + k0] = e01;
        dst[(4 * tx + 2) * NK + k0] = e02;
        dst[(4 * tx + 3) * NK + k0] = e03;
        dst[(4 * tx + 0) * NK + k0 + 1] = e10;
        dst[(4 * tx + 1) * NK + k0 + 1] = e11;
        dst[(4 * tx + 2) * NK + k0 + 1] = e12;
        dst[(4 * tx + 3) * NK + k0 + 1] = e13;
    }
}

// ---------------------------------------------------------------------------
// Fused score + softmax + context (R5-proven structure).
// Grid (NT/32, NB) = 128 blocks, 256 threads (8 warps); warp owns 4 t's,
// lane owns k = 4*lane..+3.
// score[t,k] (up to softmax-invariant const) = sum_u -2*V_u / (1 + Et*Ek),
// two u-terms share one rcp:  V0/q0 + V1/q1 = (V0*q1 + V1*q0) / (q0*q1).
// smem: know[128][256] 128KB | EkT[128][128] 64KB |
//       Et2[32][128] float2 32KB (reused as duplicated attn) | v2 1KB
//       = 230400 B (1 CTA/SM)
// ---------------------------------------------------------------------------
__global__ __launch_bounds__(256) void fused_kernel(
    const float* __restrict__ knw, const float* __restrict__ V,
    float* __restrict__ out)
{
    extern __shared__ float smem[];
    float*  know_s = smem;                          // 32768 floats
    float*  EkT_s  = smem + NK * ND;                // 16384 floats
    float2* Et2_s  = (float2*)(EkT_s + NU * NK);    // 4096 float2
    float2* v2_s   = Et2_s + 32 * NU;               // 128 float2

    const int b    = blockIdx.y;
    const int t0   = blockIdx.x * 32;
    const int tid  = threadIdx.x;
    const int lane = tid & 31;
    const int w    = tid >> 5;

    // ---- stage (float4, coalesced) ----
    {
        const float4* s = (const float4*)(knw + b * NK * ND);
        float4* d = (float4*)know_s;
        #pragma unroll
        for (int i = 0; i < 32; i++) d[tid + i * 256] = s[tid + i * 256];
    }
    {
        const float4* s = (const float4*)(g_EkT + b * NU * NK);
        float4* d = (float4*)EkT_s;
        #pragma unroll
        for (int i = 0; i < 16; i++) d[tid + i * 256] = s[tid + i * 256];
    }
    {
        const float4* s = (const float4*)(g_Et2 + (size_t)(b * NT + t0) * NU);
        float4* d = (float4*)Et2_s;
        #pragma unroll
        for (int i = 0; i < 8; i++) d[tid + i * 256] = s[tid + i * 256];
    }
    if (tid < NU) {
        float vv = -2.0f * V[tid];
        v2_s[tid] = make_float2(vv, vv);
    }
    __syncthreads();

    const int tl = 4 * w;   // first local t this warp owns

    // ---- score: acc[tt][0]=(k0,k1) packed, acc[tt][1]=(k2,k3) packed ----
    unsigned long long acc[4][2];
    #pragma unroll
    for (int tt = 0; tt < 4; tt++) { acc[tt][0] = 0ull; acc[tt][1] = 0ull; }

    #pragma unroll 2
    for (int u = 0; u < NU; u += 2) {
        ulonglong2 ek0 = ((const ulonglong2*)&EkT_s[(u + 0) * NK])[lane];
        ulonglong2 ek1 = ((const ulonglong2*)&EkT_s[(u + 1) * NK])[lane];
        unsigned long long v0 = *(const unsigned long long*)&v2_s[u + 0];
        unsigned long long v1 = *(const unsigned long long*)&v2_s[u + 1];
        #pragma unroll
        for (int tt = 0; tt < 4; tt++) {
            unsigned long long et0 =
                *(const unsigned long long*)&Et2_s[(tl + tt) * NU + u + 0];
            unsigned long long et1 =
                *(const unsigned long long*)&Et2_s[(tl + tt) * NU + u + 1];
            // k-slots (0,1)
            unsigned long long q0 = fma2(et0, ek0.x, ONE2);
            unsigned long long q1 = fma2(et1, ek1.x, ONE2);
            unsigned long long num = fma2(v0, q1, mul2(v1, q0));
            acc[tt][0] = fma2(num, rcp2(mul2(q0, q1)), acc[tt][0]);
            // k-slots (2,3)
            q0 = fma2(et0, ek0.y, ONE2);
            q1 = fma2(et1, ek1.y, ONE2);
            num = fma2(v0, q1, mul2(v1, q0));
            acc[tt][1] = fma2(num, rcp2(mul2(q0, q1)), acc[tt][1]);
        }
    }

    // ---- softmax over K (in-warp); constants cancel ----
    #pragma unroll
    for (int tt = 0; tt < 4; tt++) {
        float2 axy = u2f(acc[tt][0]);
        float2 azw = u2f(acc[tt][1]);
        float4 sv = make_float4(axy.x, axy.y, azw.x, azw.y);
        float m = fmaxf(fmaxf(sv.x, sv.y), fmaxf(sv.z, sv.w));
        #pragma unroll
        for (int o = 16; o > 0; o >>= 1)
            m = fmaxf(m, __shfl_xor_sync(0xffffffffu, m, o));
        float4 p;
        p.x = __expf(sv.x - m);
        p.y = __expf(sv.y - m);
        p.z = __expf(sv.z - m);
        p.w = __expf(sv.w - m);
        float sum = (p.x + p.y) + (p.z + p.w);
        #pragma unroll
        for (int o = 16; o > 0; o >>= 1)
            sum += __shfl_xor_sync(0xffffffffu, sum, o);
        float inv = __fdividef(1.0f, sum);
        p.x *= inv; p.y *= inv; p.z *= inv; p.w *= inv;
        // overwrite OWN Et2 row with duplicated attn (p,p); row = 128 float2
        float2* arow = Et2_s + (tl + tt) * NU;
        arow[4 * lane + 0] = make_float2(p.x, p.x);
        arow[4 * lane + 1] = make_float2(p.y, p.y);
        arow[4 * lane + 2] = make_float2(p.z, p.z);
        arow[4 * lane + 3] = make_float2(p.w, p.w);
    }
    __syncwarp();

    // ---- context (FFMA2): out[t][d] = sum_k attn[t][k] * know[k][d] ----
    unsigned long long c[4][4];
    #pragma unroll
    for (int i = 0; i < 4; i++)
        #pragma unroll
        for (int j = 0; j < 4; j++) c[i][j] = 0ull;

    #pragma unroll 4
    for (int k = 0; k < NK; k++) {
        const float* row = &know_s[k * ND];
        ulonglong2 lo = ((const ulonglong2*)row)[lane];        // d=4*lane..+3
        ulonglong2 hi = ((const ulonglong2*)row)[lane + 32];   // d=128+4*lane..+3
        #pragma unroll
        for (int tt = 0; tt < 4; tt++) {
            unsigned long long a =
                *(const unsigned long long*)&Et2_s[(tl + tt) * NU + k];
            c[tt][0] = fma2(a, lo.x, c[tt][0]);
            c[tt][1] = fma2(a, lo.y, c[tt][1]);
            c[tt][2] = fma2(a, hi.x, c[tt][2]);
            c[tt][3] = fma2(a, hi.y, c[tt][3]);
        }
    }

    #pragma unroll
    for (int tt = 0; tt < 4; tt++) {
        float* o = out + (size_t)(b * NT + t0 + tl + tt) * ND;
        ((ulonglong2*)o)[lane]      = make_ulonglong2(c[tt][0], c[tt][1]);
        ((ulonglong2*)o)[lane + 32] = make_ulonglong2(c[tt][2], c[tt][3]);
    }
}

// ---------------------------------------------------------------------------
// Launch
// ---------------------------------------------------------------------------
extern "C" void kernel_launch(void* const* d_in, const int* in_sizes, int n_in,
                              void* d_out, int out_size)
{
    const float* knw = (const float*)d_in[0];   // knowledge_onehot [16,128,256]
    const float* enc = (const float*)d_in[1];   // encoder_outputs  [16,256,256]
    const float* W1  = (const float*)d_in[2];
    const float* b1  = (const float*)d_in[3];
    const float* W2  = (const float*)d_in[4];
    const float* b2  = (const float*)d_in[5];
    const float* V   = (const float*)d_in[6];
    // d_in[7] = bV: cancels in softmax. Unused.

    if (n_in >= 2 && in_sizes[0] == NB * NT * ND && in_sizes[1] == NB * NK * ND) {
        const float* tmp = knw; knw = enc; enc = tmp;
    }

    // 32768 + 16384 + 8192 + 256 floats = 230400 bytes
    const int smem_bytes = (NK * ND + NU * NK + 32 * NU * 2 + NU * 2) * (int)sizeof(float);
    cudaFuncSetAttribute(fused_kernel, cudaFuncAttributeMaxDynamicSharedMemorySize,
                         smem_bytes);

    proj_kernel<<<384, 256>>>(enc, knw, W1, b1, W2, b2);

    dim3 grid(NT / 32, NB);
    fused_kernel<<<grid, 256, smem_bytes>>>(knw, V, (float*)d_out);

    (void)n_in; (void)out_size;
}